// round 6
// baseline (speedup 1.0000x reference)
#include <cuda_runtime.h>
#include <math.h>

#define VOCAB 50000
#define D 300
#define S 5
#define CTX 10
#define B 16384
#define XCOLS (2 + CTX)

#define THREADS 256
#define NBLOCKS ((B * 32) / THREADS)   // one warp per batch element -> 2048 blocks

// Zero at module load; last block resets after each use -> graph-replay safe.
__device__ float g_acc[S];
__device__ unsigned int g_ticket;

__global__ __launch_bounds__(THREADS, 6) void sense_fused_kernel(
    const int* __restrict__ x,
    const float* __restrict__ Wg,
    const float* __restrict__ Ws,
    float* __restrict__ out)
{
    const int gwarp = (blockIdx.x * THREADS + threadIdx.x) >> 5;
    const int lane  = threadIdx.x & 31;

    __shared__ float ssum[S];
    __shared__ float sold[S];     // consumed atomic returns (forces completion)
    if (threadIdx.x < S) ssum[threadIdx.x] = 0.0f;
    __syncthreads();

    float sc[S] = {0.f, 0.f, 0.f, 0.f, 0.f};

    {
        const int* xr = x + gwarp * XCOLS;
        const int x0 = __ldg(&xr[0]);

        const bool has3 = (lane + 64) < 75;   // 75 float4 chunks per 300-float row

        float4 c0 = make_float4(0.f, 0.f, 0.f, 0.f);
        float4 c1 = make_float4(0.f, 0.f, 0.f, 0.f);
        float4 c2 = make_float4(0.f, 0.f, 0.f, 0.f);

        #pragma unroll
        for (int j = 0; j < CTX; j++) {
            const int w = __ldg(&xr[2 + j]);
            const float4* row = (const float4*)(Wg + (size_t)w * D);
            float4 r0 = row[lane];
            float4 r1 = row[lane + 32];
            c0.x += r0.x; c0.y += r0.y; c0.z += r0.z; c0.w += r0.w;
            c1.x += r1.x; c1.y += r1.y; c1.z += r1.z; c1.w += r1.w;
            if (has3) {
                float4 r2 = row[lane + 64];
                c2.x += r2.x; c2.y += r2.y; c2.z += r2.z; c2.w += r2.w;
            }
        }

        #pragma unroll
        for (int s = 0; s < S; s++) {
            const float4* row = (const float4*)(Ws + ((size_t)x0 * S + s) * D);
            float4 r0 = row[lane];
            float4 r1 = row[lane + 32];
            float p = r0.x * c0.x + r0.y * c0.y + r0.z * c0.z + r0.w * c0.w;
            p += r1.x * c1.x + r1.y * c1.y + r1.z * c1.z + r1.w * c1.w;
            if (has3) {
                float4 r2 = row[lane + 64];
                p += r2.x * c2.x + r2.y * c2.y + r2.z * c2.z + r2.w * c2.w;
            }
            #pragma unroll
            for (int o = 16; o > 0; o >>= 1)
                p += __shfl_xor_sync(0xFFFFFFFFu, p, o);
            sc[s] = p;
        }
    }

    // block combine via shared atomics (8 warps x 5)
    if (lane == 0) {
        #pragma unroll
        for (int s = 0; s < S; s++)
            atomicAdd(&ssum[s], sc[s]);
    }
    __syncthreads();

    // Global accumulate. The return value is CONSUMED (stored to shared), so
    // the L2-side atomic has completed before the __syncthreads below --
    // this orders it ahead of the ticket increment without any fence.
    if (threadIdx.x < S)
        sold[threadIdx.x] = atomicAdd(&g_acc[threadIdx.x], ssum[threadIdx.x]);
    __syncthreads();

    __shared__ bool is_last;
    if (threadIdx.x == 0)
        is_last = (atomicAdd(&g_ticket, 1u) == (unsigned int)(NBLOCKS - 1));
    __syncthreads();

    if (is_last && threadIdx.x < S) {
        // read via the atomic path (L2) -- no stale-L1 exposure
        float v = atomicAdd(&g_acc[threadIdx.x], 0.0f);
        out[threadIdx.x] = 1.0f / (1.0f + expf(-v));
        g_acc[threadIdx.x] = 0.0f;          // reset for next call / replay
        if (threadIdx.x == 0) g_ticket = 0;
    }
    (void)sold;
}

extern "C" void kernel_launch(void* const* d_in, const int* in_sizes, int n_in,
                              void* d_out, int out_size) {
    const int*   x  = (const int*)d_in[0];
    const float* Wg = (const float*)d_in[1];
    const float* Ws = (const float*)d_in[2];
    float* out = (float*)d_out;

    sense_fused_kernel<<<NBLOCKS, THREADS>>>(x, Wg, Ws, out);
}